// round 13
// baseline (speedup 1.0000x reference)
#include <cuda_runtime.h>
#include <cuda_bf16.h>
#include <cstdint>

// ============================================================================
// LateInteractionScorer: scores[b] = sum_q max_d ( <Q[b,q], D[b,d]> + (1-mask)*(-1e30) )
// Q: [64,32,128] f32, D: [64,4096,128] f32, mask: [64,4096] i32 -> out [64] f32
//
// Base-ISA tensor path (mma.sync.m16n8k16 bf16). DRAM-bound: 134 MB doc
// stream, ~17 us floor.
//
// R13: stream doc tiles with cp.async.bulk (1D TMA bulk copy, base sm_90 ISA)
// into a depth-3 SMEM ring. The copy ENGINE keeps DRAM requests in flight
// independent of warp scheduling -- the structural fix for the 54-59% DRAM
// ceiling seen in R7/R9/R11/R12 where load issue was coupled to warps.
// One 64KB bulk per 128-doc stage (split regions are contiguous).
// ============================================================================

static constexpr int BATCH = 64;
static constexpr int QLEN  = 32;
static constexpr int DLEN  = 4096;
static constexpr int HD    = 128;

static constexpr int SPLITS = 8;
static constexpr int DOCS_PER_SPLIT = DLEN / SPLITS;   // 512
static constexpr int THREADS = 256;
static constexpr int WARPS   = THREADS / 32;           // 8
static constexpr int STAGE_DOCS = 128;                 // docs per stage
static constexpr int STAGES = DOCS_PER_SPLIT / STAGE_DOCS;  // 4
static constexpr int DEPTH  = 3;                       // ring depth

static constexpr int ROW_BYTES   = HD * 4;             // 512 (linear, matches gmem)
static constexpr int STAGE_BYTES = STAGE_DOCS * ROW_BYTES;  // 65536
static constexpr int SMEM_DYN    = DEPTH * STAGE_BYTES;     // 196608

static constexpr float NEGV = -1e30f;

// Cross-CTA scratch (zero-init at load; last CTA per batch resets after use,
// so graph replays see identical initial state). ordenc(x) > 0 for all floats,
// so 0 is the atomicMax identity.
__device__ unsigned g_qmax[BATCH * QLEN];
__device__ int      g_count[BATCH];

__device__ __forceinline__ unsigned ordenc(float f) {
    unsigned b = __float_as_uint(f);
    return (b & 0x80000000u) ? ~b : (b | 0x80000000u);
}
__device__ __forceinline__ float orddec(unsigned o) {
    unsigned b = (o & 0x80000000u) ? (o & 0x7FFFFFFFu) : ~o;
    return __uint_as_float(b);
}

__device__ __forceinline__ uint32_t packbf(float lo, float hi) {
    __nv_bfloat162 h = __floats2bfloat162_rn(lo, hi);
    return *reinterpret_cast<uint32_t*>(&h);
}

__device__ __forceinline__ void mma16816(float* c, const uint32_t* a, const uint32_t* b) {
    asm volatile(
        "mma.sync.aligned.m16n8k16.row.col.f32.bf16.bf16.f32 "
        "{%0,%1,%2,%3}, {%4,%5,%6,%7}, {%8,%9}, {%0,%1,%2,%3};"
        : "+f"(c[0]), "+f"(c[1]), "+f"(c[2]), "+f"(c[3])
        : "r"(a[0]), "r"(a[1]), "r"(a[2]), "r"(a[3]),
          "r"(b[0]), "r"(b[1]));
}

__device__ __forceinline__ uint32_t smem_u32(const void* p) {
    uint32_t a;
    asm("{ .reg .u64 t; cvta.to.shared.u64 t, %1; cvt.u32.u64 %0, t; }"
        : "=r"(a) : "l"(p));
    return a;
}

#define MBARRIER_INIT(mbar, count) \
    asm volatile("mbarrier.init.shared.b64 [%0], %1;" \
        :: "r"((uint32_t)(mbar)), "r"((uint32_t)(count)) : "memory")

#define MBARRIER_EXPECT_TX(mbar, bytes) \
    asm volatile("mbarrier.arrive.expect_tx.shared.b64 _, [%0], %1;" \
        :: "r"((uint32_t)(mbar)), "r"((uint32_t)(bytes)) : "memory")

#define MBARRIER_WAIT_PARITY(mbar_addr, phase_parity) do { \
    uint32_t _mbar = (uint32_t)(mbar_addr); \
    uint32_t _parity = (uint32_t)(phase_parity); \
    uint32_t _done; \
    asm volatile( \
        "{\n\t.reg .pred p;\n\t" \
        "mbarrier.try_wait.parity.acquire.cta.shared::cta.b64 p, [%1], %2;\n\t" \
        "selp.b32 %0, 1, 0, p;\n\t}" \
        : "=r"(_done) : "r"(_mbar), "r"(_parity) : "memory"); \
    if (!_done) { \
        asm volatile( \
            "{\n\t.reg .pred P1;\n\t" \
            "WAIT_LOOP_%=:\n\t" \
            "mbarrier.try_wait.parity.acquire.cta.shared::cta.b64 P1, [%0], %1, 0x989680;\n\t" \
            "@P1 bra.uni WAIT_DONE_%=;\n\t" \
            "bra.uni WAIT_LOOP_%=;\n\t" \
            "WAIT_DONE_%=:\n\t}" \
            :: "r"(_mbar), "r"(_parity) : "memory"); \
    } \
} while (0)

// 1D bulk copy: global -> shared, completion via mbarrier complete_tx.
__device__ __forceinline__ void bulk_copy(uint32_t dst_smem, const void* src,
                                          uint32_t bytes, uint32_t mbar) {
    asm volatile(
        "cp.async.bulk.shared::cluster.global.mbarrier::complete_tx::bytes "
        "[%0], [%1], %2, [%3];"
        :: "r"(dst_smem), "l"(src), "r"(bytes), "r"(mbar) : "memory");
}

// ---------------------------------------------------------------------------
// Fused kernel: grid (SPLITS, BATCH), 256 threads, 1 CTA/SM (smem-bound)
// ---------------------------------------------------------------------------
__global__ __launch_bounds__(THREADS)
void li_score_kernel(const float* __restrict__ qv,
                     const float* __restrict__ dv,
                     const int*   __restrict__ mask,
                     float*       __restrict__ out) {
    extern __shared__ char sbuf[];                          // DEPTH x 64KB ring
    __shared__ alignas(16) uint32_t qsm[8 * 2 * 32 * 4];    // Q frag table, 8 KB
    __shared__ float red[WARPS * QLEN];
    __shared__ int   s_last;
    __shared__ alignas(8) uint64_t mbar[DEPTH];

    const int tid  = threadIdx.x;
    const int wid  = tid >> 5;
    const int lane = tid & 31;
    const int g    = lane >> 2;   // groupID
    const int tig  = lane & 3;    // thread-in-group

    const int b     = blockIdx.y;
    const int split = blockIdx.x;

    const float* Qb = qv + (size_t)b * QLEN * HD;
    const float* Ds = dv + ((size_t)b * DLEN + (size_t)split * DOCS_PER_SPLIT) * HD;
    const int*   Mb = mask + (size_t)b * DLEN + split * DOCS_PER_SPLIT;

    const uint32_t sb_u32 = smem_u32(sbuf);
    const uint32_t mb_u32 = smem_u32(mbar);
    const char*    dsrc   = (const char*)Ds;

    // ---- Init ring barriers, then launch the first DEPTH bulk copies ----
    if (tid == 0) {
#pragma unroll
        for (int d = 0; d < DEPTH; d++) MBARRIER_INIT(mb_u32 + d * 8, 1);
    }
    __syncthreads();
    if (tid == 0) {
#pragma unroll
        for (int s = 0; s < DEPTH && s < STAGES; s++) {
            MBARRIER_EXPECT_TX(mb_u32 + s * 8, STAGE_BYTES);
            bulk_copy(sb_u32 + s * STAGE_BYTES, dsrc + (size_t)s * STAGE_BYTES,
                      STAGE_BYTES, mb_u32 + s * 8);
        }
    }

    // ---- Prefetch all mask adjustments into registers ----
    float adj0s[STAGES], adj1s[STAGES];
#pragma unroll
    for (int s = 0; s < STAGES; s++) {
        const int base = s * STAGE_DOCS + wid * 16;
        adj0s[s] = Mb[base + g]     ? 0.0f : NEGV;
        adj1s[s] = Mb[base + g + 8] ? 0.0f : NEGV;
    }

    // ---- Prologue: build B fragments in SMEM (each thread owns one (k,l)) ----
    // K-slot permutation: lane tig supplies physical dims {tig*4..tig*4+3} into
    // MMA k-slots {tig*2, tig*2+1, tig*2+8, tig*2+9}; the A side uses the same
    // permutation, so the contraction is invariant.
    {
        const int k = tid >> 5;       // 0..7
        const int l = tid & 31;
        const int lg = l >> 2, lt = l & 3;
        const int c0 = k * 16 + lt * 4;
        uint4 h0, h1;
        {
            float4 f0 = *(const float4*)(Qb + (0 * 8 + lg) * HD + c0);
            float4 f1 = *(const float4*)(Qb + (1 * 8 + lg) * HD + c0);
            h0.x = packbf(f0.x, f0.y); h0.y = packbf(f0.z, f0.w);
            h0.z = packbf(f1.x, f1.y); h0.w = packbf(f1.z, f1.w);
        }
        {
            float4 f2 = *(const float4*)(Qb + (2 * 8 + lg) * HD + c0);
            float4 f3 = *(const float4*)(Qb + (3 * 8 + lg) * HD + c0);
            h1.x = packbf(f2.x, f2.y); h1.y = packbf(f2.z, f2.w);
            h1.z = packbf(f3.x, f3.y); h1.w = packbf(f3.z, f3.w);
        }
        *(uint4*)(qsm + (k * 2 + 0) * 128 + l * 4) = h0;
        *(uint4*)(qsm + (k * 2 + 1) * 128 + l * 4) = h1;
    }
    __syncthreads();

    const uint4* qtab = (const uint4*)qsm;   // [k*2+half]*32 + lane

    float qmax[8];
#pragma unroll
    for (int i = 0; i < 8; i++) qmax[i] = -3.0e38f;

    // ---- Mainloop: consume ring stages; copy engine streams independently ----
#pragma unroll
    for (int s = 0; s < STAGES; s++) {
        const int d = s % DEPTH;
        MBARRIER_WAIT_PARITY(mb_u32 + d * 8, (s / DEPTH) & 1);

        // Warp wid consumes rows [wid*16, wid*16+16) of this 128-doc stage.
        const char* sb  = sbuf + d * STAGE_BYTES + (wid * 16) * ROW_BYTES;
        const char* r0p = sb + g * ROW_BYTES + tig * 16;
        const char* r1p = r0p + 8 * ROW_BYTES;

        float acc[4][4];
#pragma unroll
        for (int n = 0; n < 4; n++)
#pragma unroll
            for (int i = 0; i < 4; i++) acc[n][i] = 0.0f;

#pragma unroll
        for (int k = 0; k < 8; k++) {
            float4 fa0 = *(const float4*)(r0p + k * 64);    // LDS.128 (2-way conf ok)
            float4 fa1 = *(const float4*)(r1p + k * 64);
            uint4 h0 = qtab[(k * 2 + 0) * 32 + lane];       // LDS.128, n-chunks 0,1
            uint4 h1 = qtab[(k * 2 + 1) * 32 + lane];       // LDS.128, n-chunks 2,3
            uint32_t A[4];
            A[0] = packbf(fa0.x, fa0.y);
            A[1] = packbf(fa1.x, fa1.y);
            A[2] = packbf(fa0.z, fa0.w);
            A[3] = packbf(fa1.z, fa1.w);
            uint32_t B0[2] = {h0.x, h0.y}, B1[2] = {h0.z, h0.w};
            uint32_t B2[2] = {h1.x, h1.y}, B3[2] = {h1.z, h1.w};
            mma16816(acc[0], A, B0);
            mma16816(acc[1], A, B1);
            mma16816(acc[2], A, B2);
            mma16816(acc[3], A, B3);
        }

        const float adj0 = adj0s[s], adj1 = adj1s[s];
#pragma unroll
        for (int n = 0; n < 4; n++) {
            qmax[n * 2 + 0] = fmaxf(qmax[n * 2 + 0],
                                    fmaxf(acc[n][0] + adj0, acc[n][2] + adj1));
            qmax[n * 2 + 1] = fmaxf(qmax[n * 2 + 1],
                                    fmaxf(acc[n][1] + adj0, acc[n][3] + adj1));
        }

        // All warps done with buffer d -> refill it with stage s+DEPTH.
        // The copy engine keeps streaming during this sync, so DRAM stays busy.
        __syncthreads();
        if (tid == 0 && s + DEPTH < STAGES) {
            MBARRIER_EXPECT_TX(mb_u32 + d * 8, STAGE_BYTES);
            bulk_copy(sb_u32 + d * STAGE_BYTES,
                      dsrc + (size_t)(s + DEPTH) * STAGE_BYTES,
                      STAGE_BYTES, mb_u32 + d * 8);
        }
    }

    // ---- Max over the 8 groupIDs (lane bits [2:5)) ----
#pragma unroll
    for (int i = 0; i < 8; i++) {
#pragma unroll
        for (int o = 4; o <= 16; o <<= 1)
            qmax[i] = fmaxf(qmax[i], __shfl_xor_sync(0xffffffffu, qmax[i], o));
    }
    if (g == 0) {  // lanes 0..3, tig = lane
#pragma unroll
        for (int n = 0; n < 4; n++) {
            red[wid * QLEN + n * 8 + tig * 2 + 0] = qmax[n * 2 + 0];
            red[wid * QLEN + n * 8 + tig * 2 + 1] = qmax[n * 2 + 1];
        }
    }
    __syncthreads();

    // ---- Max across warps, fold into per-batch global scratch ----
    if (tid < QLEN) {
        float v = red[tid];
#pragma unroll
        for (int w = 1; w < WARPS; w++) v = fmaxf(v, red[w * QLEN + tid]);
        atomicMax(&g_qmax[b * QLEN + tid], ordenc(v));
    }
    __threadfence();

    // ---- Last CTA per batch: sum over q, write out, reset scratch ----
    if (tid == 0)
        s_last = (atomicAdd(&g_count[b], 1) == SPLITS - 1) ? 1 : 0;
    __syncthreads();

    if (s_last) {
        if (tid < QLEN) {
            unsigned o = atomicMax(&g_qmax[b * QLEN + tid], 0u);
            float v = orddec(o);
#pragma unroll
            for (int off = 16; off > 0; off >>= 1)
                v += __shfl_xor_sync(0xffffffffu, v, off);
            if (tid == 0) out[b] = v;
            g_qmax[b * QLEN + tid] = 0u;   // reset for next graph replay
        }
        if (tid == 0) g_count[b] = 0;
    }
}

// ---------------------------------------------------------------------------
extern "C" void kernel_launch(void* const* d_in, const int* in_sizes, int n_in,
                              void* d_out, int out_size) {
    const float* qv   = (const float*)d_in[0];   // [64,32,128] f32
    const float* dv   = (const float*)d_in[1];   // [64,4096,128] f32
    const int*   mask = (const int*)d_in[2];     // [64,4096] i32
    float* out = (float*)d_out;                  // [64] f32

    cudaFuncSetAttribute(li_score_kernel,
                         cudaFuncAttributeMaxDynamicSharedMemorySize, SMEM_DYN);

    dim3 grid(SPLITS, BATCH);
    li_score_kernel<<<grid, THREADS, SMEM_DYN>>>(qv, dv, mask, out);
}

// round 15
// speedup vs baseline: 1.9476x; 1.9476x over previous
#include <cuda_runtime.h>
#include <cuda_bf16.h>
#include <cstdint>

// ============================================================================
// LateInteractionScorer: scores[b] = sum_q max_d ( <Q[b,q], D[b,d]> + (1-mask)*(-1e30) )
// Q: [64,32,128] f32, D: [64,4096,128] f32, mask: [64,4096] i32 -> out [64] f32
//
// Base-ISA tensor path (mma.sync.m16n8k16 bf16).
//
// R14: ALGORITHMIC traffic cut. Masked docs (~50%, mask=randint(0,2)) get
// -1e30 and can never win the max -> never load their rows. Ballot-compact
// unmasked indices into SMEM, then gather only those rows (512B contiguous
// each -> full DRAM sector utilization). Transport = R11's proven batched
// LDG.128 body. Bytes: 134 MB -> ~68 MB.
// ============================================================================

static constexpr int BATCH = 64;
static constexpr int QLEN  = 32;
static constexpr int DLEN  = 4096;
static constexpr int HD    = 128;

static constexpr int SPLITS = 8;
static constexpr int DOCS_PER_SPLIT = DLEN / SPLITS;   // 512
static constexpr int THREADS = 256;
static constexpr int WARPS   = THREADS / 32;           // 8

static constexpr float NEGV = -1e30f;

// Cross-CTA scratch (zero-init at load; last CTA per batch resets after use,
// so graph replays see identical initial state). ordenc(x) > 0 for all floats,
// so 0 is the atomicMax identity.
__device__ unsigned g_qmax[BATCH * QLEN];
__device__ int      g_count[BATCH];

__device__ __forceinline__ unsigned ordenc(float f) {
    unsigned b = __float_as_uint(f);
    return (b & 0x80000000u) ? ~b : (b | 0x80000000u);
}
__device__ __forceinline__ float orddec(unsigned o) {
    unsigned b = (o & 0x80000000u) ? (o & 0x7FFFFFFFu) : ~o;
    return __uint_as_float(b);
}

__device__ __forceinline__ uint32_t packbf(float lo, float hi) {
    __nv_bfloat162 h = __floats2bfloat162_rn(lo, hi);
    return *reinterpret_cast<uint32_t*>(&h);
}

__device__ __forceinline__ void mma16816(float* c, const uint32_t* a, const uint32_t* b) {
    asm volatile(
        "mma.sync.aligned.m16n8k16.row.col.f32.bf16.bf16.f32 "
        "{%0,%1,%2,%3}, {%4,%5,%6,%7}, {%8,%9}, {%0,%1,%2,%3};"
        : "+f"(c[0]), "+f"(c[1]), "+f"(c[2]), "+f"(c[3])
        : "r"(a[0]), "r"(a[1]), "r"(a[2]), "r"(a[3]),
          "r"(b[0]), "r"(b[1]));
}

// ---------------------------------------------------------------------------
// Fused kernel: grid (SPLITS, BATCH), 256 threads, 2 CTAs/SM (128-reg cap)
// ---------------------------------------------------------------------------
__global__ __launch_bounds__(THREADS, 2)
void li_score_kernel(const float* __restrict__ qv,
                     const float* __restrict__ dv,
                     const int*   __restrict__ mask,
                     float*       __restrict__ out) {
    // Q B-fragment table: [k 0..8)][half 0..2)][lane 0..32)][4 x u32]
    // Lane reads 16 B at stride 16 -> conflict-free LDS.128.
    __shared__ alignas(16) uint32_t qsm[8 * 2 * 32 * 4];   // 8 KB
    __shared__ int   s_idx[DOCS_PER_SPLIT];                // compacted doc ids, 2 KB
    __shared__ int   s_cnt;
    __shared__ float red[WARPS * QLEN];
    __shared__ int   s_last;

    const int tid  = threadIdx.x;
    const int wid  = tid >> 5;
    const int lane = tid & 31;
    const int g    = lane >> 2;   // groupID
    const int tig  = lane & 3;    // thread-in-group

    const int b     = blockIdx.y;
    const int split = blockIdx.x;

    const float* Qb = qv + (size_t)b * QLEN * HD;
    const float* Ds = dv + ((size_t)b * DLEN + (size_t)split * DOCS_PER_SPLIT) * HD;
    const int*   Mb = mask + (size_t)b * DLEN + split * DOCS_PER_SPLIT;

    if (tid == 0) s_cnt = 0;
    __syncthreads();

    // ---- Phase 1: ballot-compact unmasked doc indices into s_idx ----
    // Order is arbitrary (atomicAdd) but max-fold is exact & commutative, so
    // the kernel output is deterministic.
#pragma unroll
    for (int base = 0; base < DOCS_PER_SPLIT; base += WARPS * 32) {
        const int dloc = base + wid * 32 + lane;
        const int m = Mb[dloc];
        const unsigned bal = __ballot_sync(0xffffffffu, m != 0);
        const int cnt = __popc(bal);
        const int pre = __popc(bal & ((1u << lane) - 1u));
        int wbase = 0;
        if (lane == 0 && cnt) wbase = atomicAdd(&s_cnt, cnt);
        wbase = __shfl_sync(0xffffffffu, wbase, 0);
        if (m != 0) s_idx[wbase + pre] = dloc;
    }

    // ---- Prologue: build B fragments in SMEM (each thread owns one (k,l)) ----
    // K-slot permutation: lane tig supplies physical dims {tig*4..tig*4+3} into
    // MMA k-slots {tig*2, tig*2+1, tig*2+8, tig*2+9}; the A side uses the same
    // permutation, so the contraction is invariant.
    {
        const int k = tid >> 5;       // 0..7
        const int l = tid & 31;
        const int lg = l >> 2, lt = l & 3;
        const int c0 = k * 16 + lt * 4;
        uint4 h0, h1;
        {
            float4 f0 = *(const float4*)(Qb + (0 * 8 + lg) * HD + c0);
            float4 f1 = *(const float4*)(Qb + (1 * 8 + lg) * HD + c0);
            h0.x = packbf(f0.x, f0.y); h0.y = packbf(f0.z, f0.w);
            h0.z = packbf(f1.x, f1.y); h0.w = packbf(f1.z, f1.w);
        }
        {
            float4 f2 = *(const float4*)(Qb + (2 * 8 + lg) * HD + c0);
            float4 f3 = *(const float4*)(Qb + (3 * 8 + lg) * HD + c0);
            h1.x = packbf(f2.x, f2.y); h1.y = packbf(f2.z, f2.w);
            h1.z = packbf(f3.x, f3.y); h1.w = packbf(f3.z, f3.w);
        }
        *(uint4*)(qsm + (k * 2 + 0) * 128 + l * 4) = h0;
        *(uint4*)(qsm + (k * 2 + 1) * 128 + l * 4) = h1;
    }
    __syncthreads();

    const int count = s_cnt;
    const int ngroups = max(1, (count + 15) >> 4);   // 16-doc work groups

    // Pad the tail of the list with doc 0 (L2-hot; pad slots get adj=-1e30,
    // matching reference semantics even in the all-masked corner case).
    for (int i = count + tid; i < ngroups * 16; i += THREADS) s_idx[i] = 0;
    __syncthreads();

    const uint4* qtab = (const uint4*)qsm;   // [k*2+half]*32 + lane

    float qmax[8];
#pragma unroll
    for (int i = 0; i < 8; i++) qmax[i] = -3.0e38f;

    // ---- Phase 2: warps independently consume 16-doc groups off the list ----
    for (int grp = wid; grp < ngroups; grp += WARPS) {
        const int slot0 = grp * 16 + g;
        const int slot1 = slot0 + 8;
        const int r0 = s_idx[slot0];
        const int r1 = s_idx[slot1];
        const float adj0 = (slot0 < count) ? 0.0f : NEGV;
        const float adj1 = (slot1 < count) ? 0.0f : NEGV;
        const float* row0 = Ds + (size_t)r0 * HD + tig * 4;
        const float* row1 = Ds + (size_t)r1 * HD + tig * 4;

        // Burst all 16 LDG.128 before any consumption (per-warp MLP ~16).
        float4 buf0[8], buf1[8];
#pragma unroll
        for (int k = 0; k < 8; k++) {
            buf0[k] = *(const float4*)(row0 + k * 16);
            buf1[k] = *(const float4*)(row1 + k * 16);
        }

        float acc[4][4];
#pragma unroll
        for (int n = 0; n < 4; n++)
#pragma unroll
            for (int i = 0; i < 4; i++) acc[n][i] = 0.0f;

#pragma unroll
        for (int k = 0; k < 8; k++) {
            uint4 h0 = qtab[(k * 2 + 0) * 32 + lane];       // LDS.128, n-chunks 0,1
            uint4 h1 = qtab[(k * 2 + 1) * 32 + lane];       // LDS.128, n-chunks 2,3
            uint32_t A[4];
            A[0] = packbf(buf0[k].x, buf0[k].y);
            A[1] = packbf(buf1[k].x, buf1[k].y);
            A[2] = packbf(buf0[k].z, buf0[k].w);
            A[3] = packbf(buf1[k].z, buf1[k].w);
            uint32_t B0[2] = {h0.x, h0.y}, B1[2] = {h0.z, h0.w};
            uint32_t B2[2] = {h1.x, h1.y}, B3[2] = {h1.z, h1.w};
            mma16816(acc[0], A, B0);
            mma16816(acc[1], A, B1);
            mma16816(acc[2], A, B2);
            mma16816(acc[3], A, B3);
        }

        // D frag: c0=D[g][tig*2] c1=D[g][tig*2+1] c2=D[g+8][tig*2] c3=D[g+8][tig*2+1]
#pragma unroll
        for (int n = 0; n < 4; n++) {
            qmax[n * 2 + 0] = fmaxf(qmax[n * 2 + 0],
                                    fmaxf(acc[n][0] + adj0, acc[n][2] + adj1));
            qmax[n * 2 + 1] = fmaxf(qmax[n * 2 + 1],
                                    fmaxf(acc[n][1] + adj0, acc[n][3] + adj1));
        }
    }

    // ---- Max over the 8 groupIDs (lane bits [2:5)) ----
#pragma unroll
    for (int i = 0; i < 8; i++) {
#pragma unroll
        for (int o = 4; o <= 16; o <<= 1)
            qmax[i] = fmaxf(qmax[i], __shfl_xor_sync(0xffffffffu, qmax[i], o));
    }
    if (g == 0) {  // lanes 0..3, tig = lane
#pragma unroll
        for (int n = 0; n < 4; n++) {
            red[wid * QLEN + n * 8 + tig * 2 + 0] = qmax[n * 2 + 0];
            red[wid * QLEN + n * 8 + tig * 2 + 1] = qmax[n * 2 + 1];
        }
    }
    __syncthreads();

    // ---- Max across warps, fold into per-batch global scratch ----
    if (tid < QLEN) {
        float v = red[tid];
#pragma unroll
        for (int w = 1; w < WARPS; w++) v = fmaxf(v, red[w * QLEN + tid]);
        atomicMax(&g_qmax[b * QLEN + tid], ordenc(v));
    }
    __threadfence();

    // ---- Last CTA per batch: sum over q, write out, reset scratch ----
    if (tid == 0)
        s_last = (atomicAdd(&g_count[b], 1) == SPLITS - 1) ? 1 : 0;
    __syncthreads();

    if (s_last) {
        if (tid < QLEN) {
            unsigned o = atomicMax(&g_qmax[b * QLEN + tid], 0u);
            float v = orddec(o);
#pragma unroll
            for (int off = 16; off > 0; off >>= 1)
                v += __shfl_xor_sync(0xffffffffu, v, off);
            if (tid == 0) out[b] = v;
            g_qmax[b * QLEN + tid] = 0u;   // reset for next graph replay
        }
        if (tid == 0) g_count[b] = 0;
    }
}

// ---------------------------------------------------------------------------
extern "C" void kernel_launch(void* const* d_in, const int* in_sizes, int n_in,
                              void* d_out, int out_size) {
    const float* qv   = (const float*)d_in[0];   // [64,32,128] f32
    const float* dv   = (const float*)d_in[1];   // [64,4096,128] f32
    const int*   mask = (const int*)d_in[2];     // [64,4096] i32
    float* out = (float*)d_out;                  // [64] f32

    dim3 grid(SPLITS, BATCH);
    li_score_kernel<<<grid, THREADS>>>(qv, dv, mask, out);
}